// round 7
// baseline (speedup 1.0000x reference)
#include <cuda_runtime.h>
#include <cuda_bf16.h>

#define N_NODES 131072
#define NG      4096        // graphs
#define NPG     32          // nodes per graph
#define NE      1048576     // edges per branch
#define SDIM    64
#define HDIM    128
#define CAP     64          // bucket capacity per (branch, graph)

#define NB_EDGE ((2 * NE) / (256 * 4))   // 2048 edge-filter blocks
#define NB_FOLD 32                       // fold blocks appended to k1 grid

// ---------------- scratch (device globals; zero-initialized at load) --------
// Invariant: g_cnt is all-zero before every k1 launch. Initially true (module
// load zero-init); maintained because k2 re-zeroes every counter it reads.
__device__ int   g_cnt[2][NG];
__device__ int   g_bucket[2][NG][CAP];
__device__ float g_wsd[2][2][SDIM];   // [branch][{src,dst}][s] : folded W@att

// ---------------- K1: edge filter + (in extra blocks) W@att fold ------------
__global__ void k1_filter(const int* __restrict__ upE, const int* __restrict__ dnE,
                          int is64_up, int is64_dn,
                          const float* __restrict__ upW, const float* __restrict__ upAs,
                          const float* __restrict__ upAd,
                          const float* __restrict__ dnW, const float* __restrict__ dnAs,
                          const float* __restrict__ dnAd) {
    if (blockIdx.x >= NB_EDGE) {
        // fold: one warp per output scalar w[b][v][s] = sum_h W[s,h]*att[h]
        int w = (blockIdx.x - NB_EDGE) * 8 + (threadIdx.x >> 5);  // 0..255
        int l = threadIdx.x & 31;
        int b = w >> 7;
        int v = (w >> 6) & 1;
        int s = w & 63;
        const float* W = b ? dnW : upW;
        const float* a = b ? (v ? dnAd : dnAs) : (v ? upAd : upAs);
        float4 wv = ((const float4*)(W + s * HDIM))[l];
        float4 av = ((const float4*)a)[l];
        float acc = wv.x * av.x + wv.y * av.y + wv.z * av.z + wv.w * av.w;
        #pragma unroll
        for (int o = 16; o; o >>= 1) acc += __shfl_xor_sync(0xffffffffu, acc, o);
        if (l == 0) g_wsd[b][v][s] = acc;
        return;
    }

    // edge filter: 4 edges per thread, vectorized dst reads
    long long t = (long long)blockIdx.x * blockDim.x + threadIdx.x;
    long long e4 = t * 4;
    int b = (e4 >= NE) ? 1 : 0;
    long long e = e4 - (long long)b * NE;
    const int* p = b ? dnE : upE;
    int is64 = b ? is64_dn : is64_up;

    int d[4];
    if (is64) {
        // dst low words at p[2*(NE+e) + 2k]; 4 edges = 32B = two int4 loads
        const int4* q = (const int4*)(p + 2 * (NE + e));
        int4 a0 = q[0], a1 = q[1];
        d[0] = a0.x; d[1] = a0.z; d[2] = a1.x; d[3] = a1.z;
    } else {
        int4 a0 = *(const int4*)(p + NE + e);
        d[0] = a0.x; d[1] = a0.y; d[2] = a0.z; d[3] = a0.w;
    }

    int stride = is64 ? 2 : 1;
    #pragma unroll
    for (int k = 0; k < 4; k++) {
        if ((d[k] & 31) == 31) {
            int g = d[k] >> 5;
            int src = p[(e + k) * stride];
            int pos = atomicAdd(&g_cnt[b][g], 1);
            if (pos < CAP) g_bucket[b][g][pos] = src;
        }
    }
}

// ---------------- K2: per-(graph,branch) softmax-aggregate + GEMV + fuse ----
__global__ __launch_bounds__(64) void k2_graph(
    const float* __restrict__ upx, const float* __restrict__ dnx,
    const float* __restrict__ upW, const float* __restrict__ dnW,
    const float* __restrict__ upB, const float* __restrict__ dnB,
    const float* __restrict__ mlpW, const float* __restrict__ mlpB,
    float* __restrict__ out) {

    int g = blockIdx.x;
    int b = threadIdx.x >> 5;   // warp 0 = up branch, warp 1 = down branch
    int l = threadIdx.x & 31;

    const float* x    = b ? dnx : upx;
    const float* W    = b ? dnW : upW;
    const float* bias = b ? dnB : upB;

    __shared__ int   sh_src[2][CAP];
    __shared__ float sh_xagg[2][SDIM];
    __shared__ float sh_sig[2][HDIM];

    int n = g_cnt[b][g];
    if (l == 0) g_cnt[b][g] = 0;            // restore zero-invariant for replay
    if (n > CAP) n = CAP;
    // stage bucket list in shared (coalesced, then reread via LDS)
    if (l < CAP / 2)
        ((int2*)sh_src[b])[l] = ((const int2*)g_bucket[b][g])[l];
    __syncwarp();

    // weights as float2 per lane: lane l owns dims {2l, 2l+1}
    float2 ws = ((const float2*)g_wsd[b][0])[l];
    float2 wd = ((const float2*)g_wsd[b][1])[l];

    // a_dst for the terminal node of this graph
    int dnode = g * NPG + (NPG - 1);
    float2 xd = ((const float2*)(x + dnode * SDIM))[l];
    float part = xd.x * wd.x + xd.y * wd.y;
    #pragma unroll
    for (int o = 16; o; o >>= 1) part += __shfl_xor_sync(0xffffffffu, part, o);
    float a_dst = part;

    // un-shifted softmax accumulation (logits are O(10), exp safe in fp32).
    // unroll by 2 with interleaved shuffle chains for ILP.
    float denom = 0.f, acc0 = 0.f, acc1 = 0.f;
    int i = 0;
    for (; i + 1 < n; i += 2) {
        int sa = sh_src[b][i], sb = sh_src[b][i + 1];
        float2 xa = ((const float2*)(x + sa * SDIM))[l];
        float2 xb = ((const float2*)(x + sb * SDIM))[l];
        float pa = xa.x * ws.x + xa.y * ws.y;
        float pb = xb.x * ws.x + xb.y * ws.y;
        #pragma unroll
        for (int o = 16; o; o >>= 1) {
            pa += __shfl_xor_sync(0xffffffffu, pa, o);
            pb += __shfl_xor_sync(0xffffffffu, pb, o);
        }
        float ea = pa + a_dst, eb = pb + a_dst;
        ea = ea > 0.f ? ea : 0.2f * ea;
        eb = eb > 0.f ? eb : 0.2f * eb;
        float qa = __expf(ea), qb = __expf(eb);
        denom += qa + qb;
        acc0 += qa * xa.x + qb * xb.x;
        acc1 += qa * xa.y + qb * xb.y;
    }
    if (i < n) {
        int sa = sh_src[b][i];
        float2 xa = ((const float2*)(x + sa * SDIM))[l];
        float pa = xa.x * ws.x + xa.y * ws.y;
        #pragma unroll
        for (int o = 16; o; o >>= 1) pa += __shfl_xor_sync(0xffffffffu, pa, o);
        float ea = pa + a_dst;
        ea = ea > 0.f ? ea : 0.2f * ea;
        float qa = __expf(ea);
        denom += qa;
        acc0 += qa * xa.x;
        acc1 += qa * xa.y;
    }
    float inv = 1.f / (denom + 1e-16f);

    sh_xagg[b][2 * l]     = acc0 * inv;
    sh_xagg[b][2 * l + 1] = acc1 * inv;
    __syncwarp();

    // h_out = xagg @ W  (64x128), 4 outputs per lane
    float ho0 = 0.f, ho1 = 0.f, ho2 = 0.f, ho3 = 0.f;
    #pragma unroll 8
    for (int s = 0; s < SDIM; s++) {
        float xa = sh_xagg[b][s];
        const float* Wr = W + s * HDIM;
        ho0 += xa * Wr[l];
        ho1 += xa * Wr[l + 32];
        ho2 += xa * Wr[l + 64];
        ho3 += xa * Wr[l + 96];
    }
    float hv[4] = {ho0, ho1, ho2, ho3};
    #pragma unroll
    for (int k = 0; k < 4; k++) {
        float v = hv[k] + bias[l + 32 * k];
        sh_sig[b][l + 32 * k] = 1.f / (1.f + __expf(-v));
    }
    __syncthreads();

    // fused epilogue: y[g] = sum_h sig_up*sig_dn*mlpW[h] + mlp_b
    if (b == 0) {
        float s = 0.f;
        #pragma unroll
        for (int k = 0; k < 4; k++) {
            int h = l + 32 * k;
            s += sh_sig[0][h] * sh_sig[1][h] * mlpW[h];
        }
        #pragma unroll
        for (int o = 16; o; o >>= 1) s += __shfl_xor_sync(0xffffffffu, s, o);
        if (l == 0) out[g] = s + mlpB[0];
    }
}

// ---------------- launch ----------------------------------------------------
extern "C" void kernel_launch(void* const* d_in, const int* in_sizes, int n_in,
                              void* d_out, int out_size) {
    const float* up_x  = (const float*)d_in[0];
    const int*   up_e  = (const int*)  d_in[1];
    const float* dn_x  = (const float*)d_in[3];
    const int*   dn_e  = (const int*)  d_in[4];
    const float* upW   = (const float*)d_in[6];
    const float* upAs  = (const float*)d_in[7];
    const float* upAd  = (const float*)d_in[8];
    const float* upB   = (const float*)d_in[9];
    const float* dnW   = (const float*)d_in[10];
    const float* dnAs  = (const float*)d_in[11];
    const float* dnAd  = (const float*)d_in[12];
    const float* dnB   = (const float*)d_in[13];
    const float* mlpW  = (const float*)d_in[14];
    const float* mlpB  = (const float*)d_in[15];
    float* out = (float*)d_out;

    // int64 edge tensors arrive as int32 words with doubled element count:
    // 2*2*NE = 4*NE words vs 2*NE for true int32.
    int is64_up = (in_sizes[1] >= 4 * NE) ? 1 : 0;
    int is64_dn = (in_sizes[4] >= 4 * NE) ? 1 : 0;

    k1_filter<<<NB_EDGE + NB_FOLD, 256>>>(up_e, dn_e, is64_up, is64_dn,
                                          upW, upAs, upAd, dnW, dnAs, dnAd);
    k2_graph<<<NG, 64>>>(up_x, dn_x, upW, dnW, upB, dnB, mlpW, mlpB, out);
}